// round 6
// baseline (speedup 1.0000x reference)
#include <cuda_runtime.h>
#include <cstdint>

#define N_NODES 8192
#define F_DIM   512
#define H1_DIM  32
#define H2_DIM  16
#define E_NNZ   131072

// ---------------- scratch (static device globals; no allocs) ----------------
__device__ __align__(16) float g_xw0[N_NODES * H1_DIM];   // X @ W0
__device__ __align__(16) float g_h1 [N_NODES * H1_DIM];   // spmm(A, XW0)
__device__ __align__(16) float g_t  [N_NODES * 48];       // relu(h1)@[W1|W2|W3]
__device__ __align__(16) float g_s  [N_NODES * 48];       // spmm(A, t)
__device__ __align__(16) float g_z  [N_NODES * H2_DIM];   // final latent

// ---------------- helpers -----------------------------------------------------
__device__ __forceinline__ void red_add_v4(float* p, float a, float b, float c, float d) {
    asm volatile("red.global.add.v4.f32 [%0], {%1, %2, %3, %4};"
                 :: "l"(p), "f"(a), "f"(b), "f"(c), "f"(d) : "memory");
}
__device__ __forceinline__ void fma_f32x2(unsigned long long& d,
                                          unsigned long long a,
                                          unsigned long long b) {
    asm("fma.rn.f32x2 %0, %1, %2, %0;" : "+l"(d) : "l"(a), "l"(b));
}

// ---------------- K1: XW0 = X @ W0, smem-tiled; also zeros g_h1 --------------
__global__ void __launch_bounds__(256) k_xw0(const float* __restrict__ X,
                                             const float* __restrict__ W0) {
    __shared__ float sX [64 * 64];   // [row][k]
    __shared__ float sWp[32 * 64];   // [k_pair][col*2 + parity]
    int tid  = threadIdx.x;
    int wid  = tid >> 5;
    int lane = tid & 31;
    int row0 = blockIdx.x * 64;

    // pre-zero g_h1 rows for spmm1
    {
        float4 z4 = make_float4(0.f, 0.f, 0.f, 0.f);
        reinterpret_cast<float4*>(g_h1 + (size_t)row0 * 32)[tid]       = z4;
        reinterpret_cast<float4*>(g_h1 + (size_t)row0 * 32)[tid + 256] = z4;
    }

    unsigned long long acc[8];
#pragma unroll
    for (int r = 0; r < 8; r++) acc[r] = 0ull;

    for (int k0 = 0; k0 < F_DIM; k0 += 64) {
        __syncthreads();
#pragma unroll
        for (int q = 0; q < 4; q++) {
            int idx = q * 256 + tid;
            int r   = idx >> 4;
            int c4  = idx & 15;
            float4 v = *reinterpret_cast<const float4*>(
                &X[(size_t)(row0 + r) * F_DIM + k0 + c4 * 4]);
            *reinterpret_cast<float4*>(&sX[r * 64 + c4 * 4]) = v;
        }
#pragma unroll
        for (int q = 0; q < 2; q++) {
            int idx = q * 256 + tid;
            int kk  = idx >> 3;
            int c4  = idx & 7;
            float4 v = *reinterpret_cast<const float4*>(
                &W0[(size_t)(k0 + kk) * H1_DIM + c4 * 4]);
            int k2 = kk >> 1, par = kk & 1;
            float* b = &sWp[k2 * 64 + par];
            b[(4 * c4 + 0) * 2] = v.x;
            b[(4 * c4 + 1) * 2] = v.y;
            b[(4 * c4 + 2) * 2] = v.z;
            b[(4 * c4 + 3) * 2] = v.w;
        }
        __syncthreads();

#pragma unroll
        for (int pp = 0; pp < 16; pp++) {
            unsigned long long wa = *reinterpret_cast<const unsigned long long*>(
                &sWp[(2 * pp + 0) * 64 + 2 * lane]);
            unsigned long long wb = *reinterpret_cast<const unsigned long long*>(
                &sWp[(2 * pp + 1) * 64 + 2 * lane]);
#pragma unroll
            for (int r = 0; r < 8; r++) {
                float4 xv = *reinterpret_cast<const float4*>(
                    &sX[(wid * 8 + r) * 64 + 4 * pp]);
                unsigned long long xa, xb;
                asm("mov.b64 %0, {%1, %2};" : "=l"(xa) : "f"(xv.x), "f"(xv.y));
                asm("mov.b64 %0, {%1, %2};" : "=l"(xb) : "f"(xv.z), "f"(xv.w));
                fma_f32x2(acc[r], xa, wa);
                fma_f32x2(acc[r], xb, wb);
            }
        }
    }

#pragma unroll
    for (int r = 0; r < 8; r++) {
        unsigned long long u = acc[r];
        float lo = __int_as_float((int)(u & 0xffffffffull));
        float hi = __int_as_float((int)(u >> 32));
        g_xw0[(size_t)(row0 + wid * 8 + r) * H1_DIM + lane] = lo + hi;
    }
}

// ---------------- K2: h1 = spmm(A, XW0)  (2 threads/edge, 4x red.v4) -------
__global__ void k_spmm1(const int* __restrict__ rows, const int* __restrict__ cols,
                        const float* __restrict__ vals) {
    unsigned t = blockIdx.x * blockDim.x + threadIdx.x;    // < E*2
    unsigned e = t >> 1;
    unsigned s = t & 1;
    if (e >= E_NNZ) return;
    int r = rows[e];
    int c = cols[e];
    float v = vals[e];
#pragma unroll
    for (int q = 0; q < 4; q++) {
        int off = s * 16 + q * 4;
        float4 x = *reinterpret_cast<const float4*>(&g_xw0[c * H1_DIM + off]);
        red_add_v4(&g_h1[r * H1_DIM + off], v * x.x, v * x.y, v * x.z, v * x.w);
    }
}

// ---------------- K3: t = relu(h1) @ [W1|W2|W3]  (thread per row x 6-col grp)
__global__ void k_dense2(const float* __restrict__ W1, const float* __restrict__ W2,
                         const float* __restrict__ W3) {
    __shared__ float sW[32 * 48];
    int tid = threadIdx.x;
    for (int i = tid; i < 32 * 16; i += 256) {
        int k = i >> 4, j = i & 15;
        sW[k * 48 + j]      = W1[i];
        sW[k * 48 + 16 + j] = W2[i];
        sW[k * 48 + 32 + j] = W3[i];
    }
    __syncthreads();

    int idx = blockIdx.x * 256 + tid;
    int row = idx >> 3;
    int grp = idx & 7;

#pragma unroll
    for (int j = 0; j < 6; j++) g_s[(size_t)row * 48 + grp * 6 + j] = 0.f;

    float h[32];
    const float4* hr = reinterpret_cast<const float4*>(g_h1 + row * 32);
#pragma unroll
    for (int q = 0; q < 8; q++) {
        float4 v = hr[q];
        h[4 * q + 0] = fmaxf(v.x, 0.f);
        h[4 * q + 1] = fmaxf(v.y, 0.f);
        h[4 * q + 2] = fmaxf(v.z, 0.f);
        h[4 * q + 3] = fmaxf(v.w, 0.f);
    }
    float* outp = g_t + (size_t)row * 48 + grp * 6;
    const float* wp = sW + grp * 6;
#pragma unroll
    for (int j = 0; j < 6; j++) {
        float acc = 0.f;
#pragma unroll
        for (int k = 0; k < 32; k++) acc = fmaf(h[k], wp[k * 48 + j], acc);
        outp[j] = acc;
    }
}

// ---------------- K4: s = spmm(A, t)  (4 threads/edge, 3x red.v4) ----------
__global__ void k_spmm3(const int* __restrict__ rows, const int* __restrict__ cols,
                        const float* __restrict__ vals) {
    unsigned t = blockIdx.x * blockDim.x + threadIdx.x;    // < E*4
    unsigned e = t >> 2;
    unsigned s = t & 3;
    if (e >= E_NNZ) return;
    int r  = rows[e];
    int cl = cols[e];
    float v = vals[e];
#pragma unroll
    for (int q = 0; q < 3; q++) {
        int off = s * 12 + q * 4;
        float4 x = *reinterpret_cast<const float4*>(&g_t[cl * 48 + off]);
        red_add_v4(&g_s[r * 48 + off], v * x.x, v * x.y, v * x.z, v * x.w);
    }
}

// ---------------- K5: softmax heads + double reparameterization ------------
__global__ void k_combine(const float* __restrict__ s1, const float* __restrict__ s2) {
    int tid  = threadIdx.x;
    int row  = blockIdx.x * 16 + (tid >> 4);
    int lane = tid & 15;

    float ex = g_s[row * 48 + lane];
    float x2 = g_s[row * 48 + 16 + lane];
    float x3 = g_s[row * 48 + 32 + lane];

    float m2 = x2, m3 = x3;
#pragma unroll
    for (int d = 8; d; d >>= 1) {
        m2 = fmaxf(m2, __shfl_xor_sync(0xffffffffu, m2, d));
        m3 = fmaxf(m3, __shfl_xor_sync(0xffffffffu, m3, d));
    }
    float e2 = __expf(x2 - m2), e3 = __expf(x3 - m3);
    float q2 = e2, q3 = e3;
#pragma unroll
    for (int d = 8; d; d >>= 1) {
        q2 += __shfl_xor_sync(0xffffffffu, q2, d);
        q3 += __shfl_xor_sync(0xffffffffu, q3, d);
    }
    float p2 = e2 / q2;
    float p3 = e3 / q3;
    float z_en = __expf(p2);
    float z_he = 0.1f * __expf(p3);
    float z_enn = z_en + s1[row * 16 + lane] * z_he;
    float z = ex + s2[row * 16 + lane] * z_enn;
    g_z[row * 16 + lane] = z;
}

// ---------------- K6: out = z @ z^T, 128x64 tiles, occ=2, vec writeback ----
// Staging: sm_d[128][68] (direct), sm_m[64][132] (transposed). Odd vec-count
// row strides (17 / 33 vecs) rotate row base banks so LDS.128 row reads hit
// every bank-quad exactly 4x (conflict-free); staging STS is <=2-way.
// Epilogue per thread: 16 LDS.128 + 16 STG.128 (vs 128 LDS.32 + 64 STG.32).
#define ZPAD   18
#define SD_STR 68     // 17 vecs
#define SM_STR 132    // 33 vecs
#define ZZT_SMEM_BYTES ((128 * SD_STR + 64 * SM_STR) * 4)   // 68608

__global__ void __launch_bounds__(256, 2) k_zzt(float* __restrict__ out) {
    extern __shared__ float sm[];
    float* szi  = sm;                       // [128][ZPAD] (compute phase)
    float* szj  = sm + 128 * ZPAD;          // [64][ZPAD]
    float* sm_d = sm;                       // [128][SD_STR]
    float* sm_m = sm + 128 * SD_STR;        // [64][SM_STR]

    // block -> (lower-tri square tile l, half h)
    int bx = blockIdx.x;
    int l  = bx >> 1;
    int h  = bx & 1;
    float f = sqrtf(8.0f * (float)l + 1.0f);
    int bi = (int)((f - 1.0f) * 0.5f);
    while ((bi + 1) * (bi + 2) / 2 <= l) bi++;
    while (bi * (bi + 1) / 2 > l) bi--;
    int bj = l - bi * (bi + 1) / 2;

    int i0 = bi * 128;
    int j0 = bj * 128 + h * 64;
    int tid = threadIdx.x;

    // load z tiles
#pragma unroll
    for (int q = 0; q < 2; q++) {
        int idx = q * 256 + tid;
        int r = idx >> 2;
        int c = (idx & 3) * 4;
        float4 vi = *reinterpret_cast<const float4*>(&g_z[(i0 + r) * 16 + c]);
        *reinterpret_cast<float2*>(&szi[r * ZPAD + c])     = make_float2(vi.x, vi.y);
        *reinterpret_cast<float2*>(&szi[r * ZPAD + c + 2]) = make_float2(vi.z, vi.w);
    }
    {
        int r = tid >> 2;
        int c = (tid & 3) * 4;
        float4 vj = *reinterpret_cast<const float4*>(&g_z[(j0 + r) * 16 + c]);
        *reinterpret_cast<float2*>(&szj[r * ZPAD + c])     = make_float2(vj.x, vj.y);
        *reinterpret_cast<float2*>(&szj[r * ZPAD + c + 2]) = make_float2(vj.z, vj.w);
    }
    __syncthreads();

    int ti = tid >> 4;    // 0..15 : rows ti+16r
    int tj = tid & 15;    // 0..15 : cols tj+16c (c<4)

    unsigned long long acc[8][4];
#pragma unroll
    for (int r = 0; r < 8; r++)
#pragma unroll
        for (int c = 0; c < 4; c++) acc[r][c] = 0ull;

#pragma unroll
    for (int kp = 0; kp < 8; kp++) {
        unsigned long long a[8], b[4];
#pragma unroll
        for (int r = 0; r < 8; r++)
            a[r] = *reinterpret_cast<const unsigned long long*>(
                &szi[(ti + 16 * r) * ZPAD + 2 * kp]);
#pragma unroll
        for (int c = 0; c < 4; c++)
            b[c] = *reinterpret_cast<const unsigned long long*>(
                &szj[(tj + 16 * c) * ZPAD + 2 * kp]);
#pragma unroll
        for (int r = 0; r < 8; r++)
#pragma unroll
            for (int c = 0; c < 4; c++) fma_f32x2(acc[r][c], a[r], b[c]);
    }
    __syncthreads();   // reuse smem as staging

    bool mirror = (bi != bj);

#pragma unroll
    for (int r = 0; r < 8; r++)
#pragma unroll
        for (int c = 0; c < 4; c++) {
            unsigned long long u = acc[r][c];
            float lo = __int_as_float((int)(u & 0xffffffffull));
            float hi = __int_as_float((int)(u >> 32));
            float v = lo + hi;
            int row = ti + 16 * r;
            int col = tj + 16 * c;
            sm_d[row * SD_STR + col] = v;
            if (mirror) sm_m[col * SM_STR + row] = v;
        }
    __syncthreads();

    int lane = tid & 31;
    int w    = tid >> 5;       // 0..7
    int l15  = lane & 15;
    int hi16 = lane >> 4;

    // direct tile: 2 rows per warp-iter, LDS.128 + STG.128 (256B per half-warp)
#pragma unroll
    for (int m = 0; m < 8; m++) {
        int row = 16 * m + 2 * w + hi16;
        float4 v = *reinterpret_cast<const float4*>(&sm_d[row * SD_STR + 4 * l15]);
        *reinterpret_cast<float4*>(
            &out[(size_t)(i0 + row) * N_NODES + j0 + 4 * l15]) = v;
    }

    // mirror tile: 1 row (128 floats) per warp-iter, 512B contiguous STG
    if (mirror) {
#pragma unroll
        for (int m = 0; m < 8; m++) {
            int j = 8 * w + m;
            float4 v = *reinterpret_cast<const float4*>(&sm_m[j * SM_STR + 4 * lane]);
            *reinterpret_cast<float4*>(
                &out[(size_t)(j0 + j) * N_NODES + i0 + 4 * lane]) = v;
        }
    }
}

// ---------------- launcher ---------------------------------------------------
extern "C" void kernel_launch(void* const* d_in, const int* in_sizes, int n_in,
                              void* d_out, int out_size) {
    const float* features = (const float*)d_in[0];
    const int*   adj_rows = (const int*)  d_in[1];
    const int*   adj_cols = (const int*)  d_in[2];
    const float* adj_val  = (const float*)d_in[3];
    const float* W0       = (const float*)d_in[4];
    const float* W1       = (const float*)d_in[5];
    const float* W2       = (const float*)d_in[6];
    const float* W3       = (const float*)d_in[7];
    const float* sample_1 = (const float*)d_in[8];
    const float* sample_2 = (const float*)d_in[9];
    float* out = (float*)d_out;

    cudaFuncSetAttribute(k_zzt, cudaFuncAttributeMaxDynamicSharedMemorySize,
                         ZZT_SMEM_BYTES);

    k_xw0<<<N_NODES / 64, 256>>>(features, W0);
    k_spmm1<<<E_NNZ * 2 / 256, 256>>>(adj_rows, adj_cols, adj_val);
    k_dense2<<<N_NODES * 8 / 256, 256>>>(W1, W2, W3);
    k_spmm3<<<E_NNZ * 4 / 256, 256>>>(adj_rows, adj_cols, adj_val);
    k_combine<<<N_NODES / 16, 256>>>(sample_1, sample_2);

    int ntiles = (N_NODES / 128) * (N_NODES / 128 + 1) / 2;   // 2080
    k_zzt<<<ntiles * 2, 256, ZZT_SMEM_BYTES>>>(out);
}

// round 7
// speedup vs baseline: 1.0610x; 1.0610x over previous
#include <cuda_runtime.h>
#include <cstdint>

#define N_NODES 8192
#define F_DIM   512
#define H1_DIM  32
#define H2_DIM  16
#define E_NNZ   131072

// ---------------- scratch (static device globals; no allocs) ----------------
__device__ __align__(16) float g_xw0[N_NODES * H1_DIM];   // X @ W0
__device__ __align__(16) float g_h1 [N_NODES * H1_DIM];   // spmm(A, XW0)
__device__ __align__(16) float g_t  [N_NODES * 48];       // relu(h1)@[W1|W2|W3]
__device__ __align__(16) float g_s  [N_NODES * 48];       // spmm(A, t)
__device__ __align__(16) float g_z  [N_NODES * H2_DIM];   // final latent

// ---------------- helpers -----------------------------------------------------
__device__ __forceinline__ void red_add_v4(float* p, float a, float b, float c, float d) {
    asm volatile("red.global.add.v4.f32 [%0], {%1, %2, %3, %4};"
                 :: "l"(p), "f"(a), "f"(b), "f"(c), "f"(d) : "memory");
}
__device__ __forceinline__ void fma_f32x2(unsigned long long& d,
                                          unsigned long long a,
                                          unsigned long long b) {
    asm("fma.rn.f32x2 %0, %1, %2, %0;" : "+l"(d) : "l"(a), "l"(b));
}

// ---------------- K1: XW0 = X @ W0, smem-tiled; also zeros g_h1 --------------
__global__ void __launch_bounds__(256) k_xw0(const float* __restrict__ X,
                                             const float* __restrict__ W0) {
    __shared__ float sX [64 * 64];   // [row][k]
    __shared__ float sWp[32 * 64];   // [k_pair][col*2 + parity]
    int tid  = threadIdx.x;
    int wid  = tid >> 5;
    int lane = tid & 31;
    int row0 = blockIdx.x * 64;

    // pre-zero g_h1 rows for spmm1
    {
        float4 z4 = make_float4(0.f, 0.f, 0.f, 0.f);
        reinterpret_cast<float4*>(g_h1 + (size_t)row0 * 32)[tid]       = z4;
        reinterpret_cast<float4*>(g_h1 + (size_t)row0 * 32)[tid + 256] = z4;
    }

    unsigned long long acc[8];
#pragma unroll
    for (int r = 0; r < 8; r++) acc[r] = 0ull;

    for (int k0 = 0; k0 < F_DIM; k0 += 64) {
        __syncthreads();
#pragma unroll
        for (int q = 0; q < 4; q++) {
            int idx = q * 256 + tid;
            int r   = idx >> 4;
            int c4  = idx & 15;
            float4 v = *reinterpret_cast<const float4*>(
                &X[(size_t)(row0 + r) * F_DIM + k0 + c4 * 4]);
            *reinterpret_cast<float4*>(&sX[r * 64 + c4 * 4]) = v;
        }
#pragma unroll
        for (int q = 0; q < 2; q++) {
            int idx = q * 256 + tid;
            int kk  = idx >> 3;
            int c4  = idx & 7;
            float4 v = *reinterpret_cast<const float4*>(
                &W0[(size_t)(k0 + kk) * H1_DIM + c4 * 4]);
            int k2 = kk >> 1, par = kk & 1;
            float* b = &sWp[k2 * 64 + par];
            b[(4 * c4 + 0) * 2] = v.x;
            b[(4 * c4 + 1) * 2] = v.y;
            b[(4 * c4 + 2) * 2] = v.z;
            b[(4 * c4 + 3) * 2] = v.w;
        }
        __syncthreads();

#pragma unroll
        for (int pp = 0; pp < 16; pp++) {
            unsigned long long wa = *reinterpret_cast<const unsigned long long*>(
                &sWp[(2 * pp + 0) * 64 + 2 * lane]);
            unsigned long long wb = *reinterpret_cast<const unsigned long long*>(
                &sWp[(2 * pp + 1) * 64 + 2 * lane]);
#pragma unroll
            for (int r = 0; r < 8; r++) {
                float4 xv = *reinterpret_cast<const float4*>(
                    &sX[(wid * 8 + r) * 64 + 4 * pp]);
                unsigned long long xa, xb;
                asm("mov.b64 %0, {%1, %2};" : "=l"(xa) : "f"(xv.x), "f"(xv.y));
                asm("mov.b64 %0, {%1, %2};" : "=l"(xb) : "f"(xv.z), "f"(xv.w));
                fma_f32x2(acc[r], xa, wa);
                fma_f32x2(acc[r], xb, wb);
            }
        }
    }

#pragma unroll
    for (int r = 0; r < 8; r++) {
        unsigned long long u = acc[r];
        float lo = __int_as_float((int)(u & 0xffffffffull));
        float hi = __int_as_float((int)(u >> 32));
        g_xw0[(size_t)(row0 + wid * 8 + r) * H1_DIM + lane] = lo + hi;
    }
}

// ---------------- K2: h1 = spmm(A, XW0)  (8 threads/edge, red.v4) ----------
__global__ void k_spmm1(const int* __restrict__ rows, const int* __restrict__ cols,
                        const float* __restrict__ vals) {
    unsigned t = blockIdx.x * blockDim.x + threadIdx.x;    // < E*8
    unsigned e = t >> 3;
    unsigned s = t & 7;
    if (e >= E_NNZ) return;
    int r = rows[e];
    int c = cols[e];
    float v = vals[e];
    float4 x = *reinterpret_cast<const float4*>(&g_xw0[c * H1_DIM + s * 4]);
    red_add_v4(&g_h1[r * H1_DIM + s * 4], v * x.x, v * x.y, v * x.z, v * x.w);
}

// ---------------- K3: t = relu(h1) @ [W1|W2|W3]  (thread per row x 6-col grp)
__global__ void k_dense2(const float* __restrict__ W1, const float* __restrict__ W2,
                         const float* __restrict__ W3) {
    __shared__ float sW[32 * 48];
    int tid = threadIdx.x;
    for (int i = tid; i < 32 * 16; i += 256) {
        int k = i >> 4, j = i & 15;
        sW[k * 48 + j]      = W1[i];
        sW[k * 48 + 16 + j] = W2[i];
        sW[k * 48 + 32 + j] = W3[i];
    }
    __syncthreads();

    int idx = blockIdx.x * 256 + tid;
    int row = idx >> 3;
    int grp = idx & 7;

#pragma unroll
    for (int j = 0; j < 6; j++) g_s[(size_t)row * 48 + grp * 6 + j] = 0.f;

    float h[32];
    const float4* hr = reinterpret_cast<const float4*>(g_h1 + row * 32);
#pragma unroll
    for (int q = 0; q < 8; q++) {
        float4 v = hr[q];
        h[4 * q + 0] = fmaxf(v.x, 0.f);
        h[4 * q + 1] = fmaxf(v.y, 0.f);
        h[4 * q + 2] = fmaxf(v.z, 0.f);
        h[4 * q + 3] = fmaxf(v.w, 0.f);
    }
    float* outp = g_t + (size_t)row * 48 + grp * 6;
    const float* wp = sW + grp * 6;
#pragma unroll
    for (int j = 0; j < 6; j++) {
        float acc = 0.f;
#pragma unroll
        for (int k = 0; k < 32; k++) acc = fmaf(h[k], wp[k * 48 + j], acc);
        outp[j] = acc;
    }
}

// ---------------- K4: s = spmm(A, t)  (12 threads/edge, red.v4) ------------
__global__ void k_spmm3(const int* __restrict__ rows, const int* __restrict__ cols,
                        const float* __restrict__ vals) {
    unsigned t = blockIdx.x * blockDim.x + threadIdx.x;    // < E*12
    unsigned e = t / 12u;
    unsigned s = t - e * 12u;
    if (e >= E_NNZ) return;
    int r  = rows[e];
    int cl = cols[e];
    float v = vals[e];
    float4 x = *reinterpret_cast<const float4*>(&g_t[cl * 48 + s * 4]);
    red_add_v4(&g_s[r * 48 + s * 4], v * x.x, v * x.y, v * x.z, v * x.w);
}

// ---------------- K5: softmax heads + double reparameterization ------------
__global__ void k_combine(const float* __restrict__ s1, const float* __restrict__ s2) {
    int tid  = threadIdx.x;
    int row  = blockIdx.x * 16 + (tid >> 4);
    int lane = tid & 15;

    float ex = g_s[row * 48 + lane];
    float x2 = g_s[row * 48 + 16 + lane];
    float x3 = g_s[row * 48 + 32 + lane];

    float m2 = x2, m3 = x3;
#pragma unroll
    for (int d = 8; d; d >>= 1) {
        m2 = fmaxf(m2, __shfl_xor_sync(0xffffffffu, m2, d));
        m3 = fmaxf(m3, __shfl_xor_sync(0xffffffffu, m3, d));
    }
    float e2 = __expf(x2 - m2), e3 = __expf(x3 - m3);
    float q2 = e2, q3 = e3;
#pragma unroll
    for (int d = 8; d; d >>= 1) {
        q2 += __shfl_xor_sync(0xffffffffu, q2, d);
        q3 += __shfl_xor_sync(0xffffffffu, q3, d);
    }
    float p2 = e2 / q2;
    float p3 = e3 / q3;
    float z_en = __expf(p2);
    float z_he = 0.1f * __expf(p3);
    float z_enn = z_en + s1[row * 16 + lane] * z_he;
    float z = ex + s2[row * 16 + lane] * z_enn;
    g_z[row * 16 + lane] = z;
}

// ---------------- K6: out = z @ z^T, 128x64 tiles, occ=2 -------------------
// Direct tile: stored STRAIGHT FROM REGISTERS (half-warp writes 64B contiguous
// per (r,c) -> coalesced STG.32, zero smem traffic, no extra syncs).
// Mirror tile: staged in sm_m[64][132] (odd-vec stride: <=2-way STS,
// conflict-free LDS.128), written as 64 rows x 512B STG.128 streams.
#define ZPAD   18
#define SM_STR 132    // 33 vecs
#define ZZT_SMEM_BYTES (64 * SM_STR * 4)   // 33792; compute phase needs 13824

__global__ void __launch_bounds__(256, 2) k_zzt(float* __restrict__ out) {
    extern __shared__ float sm[];
    float* szi  = sm;                       // [128][ZPAD] (compute phase)
    float* szj  = sm + 128 * ZPAD;          // [64][ZPAD]
    float* sm_m = sm;                       // [64][SM_STR] (staging, overlaps)

    // block -> (lower-tri square tile l, half h)
    int bx = blockIdx.x;
    int l  = bx >> 1;
    int h  = bx & 1;
    float f = sqrtf(8.0f * (float)l + 1.0f);
    int bi = (int)((f - 1.0f) * 0.5f);
    while ((bi + 1) * (bi + 2) / 2 <= l) bi++;
    while (bi * (bi + 1) / 2 > l) bi--;
    int bj = l - bi * (bi + 1) / 2;

    int i0 = bi * 128;
    int j0 = bj * 128 + h * 64;
    int tid = threadIdx.x;

    // load z tiles
#pragma unroll
    for (int q = 0; q < 2; q++) {
        int idx = q * 256 + tid;
        int r = idx >> 2;
        int c = (idx & 3) * 4;
        float4 vi = *reinterpret_cast<const float4*>(&g_z[(i0 + r) * 16 + c]);
        *reinterpret_cast<float2*>(&szi[r * ZPAD + c])     = make_float2(vi.x, vi.y);
        *reinterpret_cast<float2*>(&szi[r * ZPAD + c + 2]) = make_float2(vi.z, vi.w);
    }
    {
        int r = tid >> 2;
        int c = (tid & 3) * 4;
        float4 vj = *reinterpret_cast<const float4*>(&g_z[(j0 + r) * 16 + c]);
        *reinterpret_cast<float2*>(&szj[r * ZPAD + c])     = make_float2(vj.x, vj.y);
        *reinterpret_cast<float2*>(&szj[r * ZPAD + c + 2]) = make_float2(vj.z, vj.w);
    }
    __syncthreads();

    int ti = tid >> 4;    // 0..15 : rows ti+16r
    int tj = tid & 15;    // 0..15 : cols tj+16c (c<4)

    unsigned long long acc[8][4];
#pragma unroll
    for (int r = 0; r < 8; r++)
#pragma unroll
        for (int c = 0; c < 4; c++) acc[r][c] = 0ull;

#pragma unroll
    for (int kp = 0; kp < 8; kp++) {
        unsigned long long a[8], b[4];
#pragma unroll
        for (int r = 0; r < 8; r++)
            a[r] = *reinterpret_cast<const unsigned long long*>(
                &szi[(ti + 16 * r) * ZPAD + 2 * kp]);
#pragma unroll
        for (int c = 0; c < 4; c++)
            b[c] = *reinterpret_cast<const unsigned long long*>(
                &szj[(tj + 16 * c) * ZPAD + 2 * kp]);
#pragma unroll
        for (int r = 0; r < 8; r++)
#pragma unroll
            for (int c = 0; c < 4; c++) fma_f32x2(acc[r][c], a[r], b[c]);
    }

    bool mirror = (bi != bj);

    // finalize values; store direct tile straight from registers
    float res[8][4];
#pragma unroll
    for (int r = 0; r < 8; r++)
#pragma unroll
        for (int c = 0; c < 4; c++) {
            unsigned long long u = acc[r][c];
            float lo = __int_as_float((int)(u & 0xffffffffull));
            float hi = __int_as_float((int)(u >> 32));
            res[r][c] = lo + hi;
            out[(size_t)(i0 + ti + 16 * r) * N_NODES + j0 + tj + 16 * c] = res[r][c];
        }

    // mirror tile via smem transpose staging
    if (mirror) {
        __syncthreads();    // compute-phase smem reads done before overwrite
#pragma unroll
        for (int r = 0; r < 8; r++)
#pragma unroll
            for (int c = 0; c < 4; c++)
                sm_m[(tj + 16 * c) * SM_STR + ti + 16 * r] = res[r][c];
        __syncthreads();

        int lane = tid & 31;
        int w    = tid >> 5;   // 0..7
#pragma unroll
        for (int m = 0; m < 8; m++) {
            int j = 8 * w + m;
            float4 v = *reinterpret_cast<const float4*>(&sm_m[j * SM_STR + 4 * lane]);
            *reinterpret_cast<float4*>(
                &out[(size_t)(j0 + j) * N_NODES + i0 + 4 * lane]) = v;
        }
    }
}

// ---------------- launcher ---------------------------------------------------
extern "C" void kernel_launch(void* const* d_in, const int* in_sizes, int n_in,
                              void* d_out, int out_size) {
    const float* features = (const float*)d_in[0];
    const int*   adj_rows = (const int*)  d_in[1];
    const int*   adj_cols = (const int*)  d_in[2];
    const float* adj_val  = (const float*)d_in[3];
    const float* W0       = (const float*)d_in[4];
    const float* W1       = (const float*)d_in[5];
    const float* W2       = (const float*)d_in[6];
    const float* W3       = (const float*)d_in[7];
    const float* sample_1 = (const float*)d_in[8];
    const float* sample_2 = (const float*)d_in[9];
    float* out = (float*)d_out;

    cudaFuncSetAttribute(k_zzt, cudaFuncAttributeMaxDynamicSharedMemorySize,
                         ZZT_SMEM_BYTES);

    k_xw0<<<N_NODES / 64, 256>>>(features, W0);
    k_spmm1<<<E_NNZ * 8 / 256, 256>>>(adj_rows, adj_cols, adj_val);
    k_dense2<<<N_NODES * 8 / 256, 256>>>(W1, W2, W3);
    k_spmm3<<<(E_NNZ * 12) / 256, 256>>>(adj_rows, adj_cols, adj_val);
    k_combine<<<N_NODES / 16, 256>>>(sample_1, sample_2);

    int ntiles = (N_NODES / 128) * (N_NODES / 128 + 1) / 2;   // 2080
    k_zzt<<<ntiles * 2, 256, ZZT_SMEM_BYTES>>>(out);
}